// round 15
// baseline (speedup 1.0000x reference)
#include <cuda_runtime.h>
#include <math.h>

#define B_ 2
#define S_ 2048
#define E_ 1024
#define H_ 16
#define D_ 64

typedef unsigned int u32;

// Scratch (device globals — no allocation allowed in kernel_launch)
// g_Q/g_K: [B,H,S,D] with d-permutation pi (pairs (t,t+4) adjacent), tf32,
//          Q pre-scaled by 1/8.  g_V: [B,H,D,S] tf32.  Consumed only by attn.
__device__ float g_Q [B_ * S_ * E_];
__device__ float g_K [B_ * S_ * E_];
__device__ float g_V [B_ * S_ * E_];
__device__ float g_AO[B_ * S_ * E_];   // [B,S,E]

__device__ __forceinline__ u32 tf32b(float x) {   // tf32 (rna) bit pattern
    u32 r; asm("cvt.rna.tf32.f32 %0, %1;" : "=r"(r) : "f"(x));
    return r;
}
__device__ __forceinline__ float tf32r(float x) {
    return __uint_as_float(tf32b(x));
}
// D += A(16x8, row) * B(8x8, col)  -- tf32 inputs, fp32 accum (sm_80+ baseline)
__device__ __forceinline__ void mma8(float* c, const u32* a, const u32* b) {
    asm volatile(
        "mma.sync.aligned.m16n8k8.row.col.f32.tf32.tf32.f32 "
        "{%0,%1,%2,%3}, {%4,%5,%6,%7}, {%8,%9}, {%0,%1,%2,%3};"
        : "+f"(c[0]), "+f"(c[1]), "+f"(c[2]), "+f"(c[3])
        : "r"(a[0]), "r"(a[1]), "r"(a[2]), "r"(a[3]), "r"(b[0]), "r"(b[1]));
}
__device__ __forceinline__ void mma8v(float* c, u32 a0, u32 a1, u32 a2, u32 a3,
                                      u32 b0, u32 b1) {
    asm volatile(
        "mma.sync.aligned.m16n8k8.row.col.f32.tf32.tf32.f32 "
        "{%0,%1,%2,%3}, {%4,%5,%6,%7}, {%8,%9}, {%0,%1,%2,%3};"
        : "+f"(c[0]), "+f"(c[1]), "+f"(c[2]), "+f"(c[3])
        : "r"(a0), "r"(a1), "r"(a2), "r"(a3), "r"(b0), "r"(b1));
}
__device__ __forceinline__ u32 smem_u32(const void* p) {
    u32 a;
    asm("{ .reg .u64 t; cvta.to.shared.u64 t, %1; cvt.u32.u64 %0, t; }"
        : "=r"(a) : "l"(p));
    return a;
}
#define CP16(d, s) \
    asm volatile("cp.async.ca.shared.global [%0], [%1], 16;" :: "r"(d), "l"(s))
#define CPCOMMIT() asm volatile("cp.async.commit_group;" ::: "memory")
#define CPWAIT1()  asm volatile("cp.async.wait_group 1;" ::: "memory")

// d-permutation within each 8-group: t<4 -> 2t ; t>=4 -> 2(t-4)+1
__device__ __forceinline__ int dperm(int c) {
    const int t = c & 7;
    return (c & ~7) + ((t < 4) ? 2 * t : 2 * (t - 4) + 1);
}

// ============================================================================
// tf32 mma.sync GEMM: C[4096,1024] = A[M,K] @ Bw[N,K]^T
// CTA tile 128x128, BK=32, 8 warps (2m x 4n), warp tile 64x32.
// MODE 0: C[M,N] fp32.
// MODE 1: [B,H,S,D], tf32, scaled, d-PERMUTED (attention Q/K prep).
// MODE 2: [B,H,D,S], tf32 (V transposed for attention).
// ============================================================================
template <int MODE>
__global__ __launch_bounds__(256) void gemm_mma(const float* __restrict__ A,
                                                const float* __restrict__ Bw,
                                                float* __restrict__ C,
                                                float scale) {
    __shared__ float As[128][36];   // [m][k]
    __shared__ float Bs[128][36];   // [n][k]

    const int tid = threadIdx.x;
    const int wid = tid >> 5, lane = tid & 31;
    const int g = lane >> 2, tig = lane & 3;
    const int wm = wid >> 2, wn = wid & 3;
    const int m0 = blockIdx.y * 128, n0 = blockIdx.x * 128;

    const int row = tid >> 1, half = tid & 1;
    const float* pA = A  + (size_t)(m0 + row) * E_ + half * 16;
    const float* pB = Bw + (size_t)(n0 + row) * E_ + half * 16;

    float acc[4][4][4];
#pragma unroll
    for (int i = 0; i < 4; i++)
#pragma unroll
        for (int j = 0; j < 4; j++)
#pragma unroll
            for (int r = 0; r < 4; r++) acc[i][j][r] = 0.f;

    float4 fa[4], fb[4];
#pragma unroll
    for (int u = 0; u < 4; u++) {
        fa[u] = *(const float4*)(pA + u * 4);
        fb[u] = *(const float4*)(pB + u * 4);
    }

    for (int c = 0; c < 32; c++) {
#pragma unroll
        for (int u = 0; u < 4; u++) {
            const int kc = half * 16 + u * 4;
            *(float4*)&As[row][kc] = make_float4(tf32r(fa[u].x), tf32r(fa[u].y),
                                                 tf32r(fa[u].z), tf32r(fa[u].w));
            *(float4*)&Bs[row][kc] = make_float4(tf32r(fb[u].x), tf32r(fb[u].y),
                                                 tf32r(fb[u].z), tf32r(fb[u].w));
        }
        __syncthreads();
        if (c + 1 < 32) {
#pragma unroll
            for (int u = 0; u < 4; u++) {
                fa[u] = *(const float4*)(pA + (c + 1) * 32 + u * 4);
                fb[u] = *(const float4*)(pB + (c + 1) * 32 + u * 4);
            }
        }
#pragma unroll
        for (int k8 = 0; k8 < 32; k8 += 8) {
            u32 a[4][4], b[4][2];
#pragma unroll
            for (int mi = 0; mi < 4; mi++) {
                const int r = wm * 64 + mi * 16 + g;
                const u32* r0 = (const u32*)&As[r][k8 + tig];
                const u32* r1 = (const u32*)&As[r + 8][k8 + tig];
                a[mi][0] = r0[0]; a[mi][1] = r1[0];
                a[mi][2] = r0[4]; a[mi][3] = r1[4];
            }
#pragma unroll
            for (int ni = 0; ni < 4; ni++) {
                const int nn = wn * 32 + ni * 8 + g;
                const u32* r0 = (const u32*)&Bs[nn][k8 + tig];
                b[ni][0] = r0[0]; b[ni][1] = r0[4];
            }
#pragma unroll
            for (int mi = 0; mi < 4; mi++)
#pragma unroll
                for (int ni = 0; ni < 4; ni++)
                    mma8(acc[mi][ni], a[mi], b[ni]);
        }
        __syncthreads();
    }

#pragma unroll
    for (int mi = 0; mi < 4; mi++) {
#pragma unroll
        for (int hh = 0; hh < 2; hh++) {
            const int mg = m0 + wm * 64 + mi * 16 + g + hh * 8;
#pragma unroll
            for (int ni = 0; ni < 4; ni++) {
                const int col = n0 + wn * 32 + ni * 8 + 2 * tig;
                const float v0 = acc[mi][ni][hh * 2 + 0];
                const float v1 = acc[mi][ni][hh * 2 + 1];
                if (MODE == 0) {
                    *(float2*)&C[(size_t)mg * E_ + col] = make_float2(v0, v1);
                } else {
                    const int b = mg >> 11, s = mg & 2047;
                    const int h = col >> 6, d = col & 63;
                    if (MODE == 1) {   // d-permuted scalar stores
                        float* base = &C[((size_t)(b * H_ + h) * S_ + s) * D_];
                        base[dperm(d)]     = tf32r(v0 * scale);
                        base[dperm(d + 1)] = tf32r(v1 * scale);
                    } else {  // MODE 2: [B,H,D,S]
                        C[((size_t)(b * H_ + h) * D_ + d)     * S_ + s] = tf32r(v0 * scale);
                        C[((size_t)(b * H_ + h) * D_ + d + 1) * S_ + s] = tf32r(v1 * scale);
                    }
                }
            }
        }
    }
}

// ============================================================================
// tf32 mma.sync flash attention, cp.async double-buffered.
// CTA: 128 q-rows x one (b,h); 128 threads = 4 warps, EACH warp owns TWO
// 16-row q-tiles (32 q).  Every K/V B-fragment LDS.64 feeds 2 mmas and each
// cp.async key-tile serves 128 q -> LSU cycles per q halved vs round 13.
// Q/K arrive d-permuted (frag pairs adjacent); V as [D,S].
// Ks/Vt stride 72 (== 8 mod 32): 64-bit frag loads conflict-free per phase.
// ============================================================================
#define KST 72
#define TILEF (64 * KST)             // floats per array per stage
#define SMEM_ATTN (4 * TILEF * 4)    // K0,K1,V0,V1 = 73728 B

__global__ void __launch_bounds__(128)
attn_mma(const float* __restrict__ Q, const float* __restrict__ K,
         const float* __restrict__ V, float* __restrict__ AO) {
    extern __shared__ __align__(16) float sm[];
    const int tid = threadIdx.x;
    const int w = tid >> 5, lane = tid & 31;
    const int g = lane >> 2, tig = lane & 3;
    const int bh = blockIdx.y;
    const int q0 = blockIdx.x * 128;

    const float* Qb = Q + (size_t)bh * S_ * D_;
    const float* Kb = K + (size_t)bh * S_ * D_;
    const float* Vb = V + (size_t)bh * D_ * S_;   // [D,S]

    const u32 sbase = smem_u32(sm);
    const int fr = tid >> 1;            // fill row (key / d)
    const int fh = (tid & 1) * 32;      // fill col half (floats)

#define PREFETCH(k0v, bbuf) do {                                               \
    const u32 kd = sbase + (u32)(((bbuf) * TILEF + fr * KST + fh) * 4);        \
    const float* ksrc = Kb + (size_t)((k0v) + fr) * D_ + fh;                   \
    const u32 vd = sbase + (u32)(((2 + (bbuf)) * TILEF + fr * KST + fh) * 4);  \
    const float* vsrc = Vb + (size_t)fr * S_ + (k0v) + fh;                     \
    _Pragma("unroll")                                                          \
    for (int c2 = 0; c2 < 8; c2++) {                                           \
        CP16(kd + c2 * 16, ksrc + c2 * 4);                                     \
        CP16(vd + c2 * 16, vsrc + c2 * 4);                                     \
    }                                                                          \
} while (0)

    PREFETCH(0, 0);
    CPCOMMIT();

    // ---- Q fragments for both tiles (permuted pairs -> 8B loads) ----
    u32 qf[2][8][4];
#pragma unroll
    for (int t = 0; t < 2; t++) {
        const int r = q0 + w * 32 + t * 16 + g;
#pragma unroll
        for (int k8 = 0; k8 < 8; k8++) {
            const float2 a = *(const float2*)&Qb[(size_t)r * D_ + k8 * 8 + 2 * tig];
            const float2 b = *(const float2*)&Qb[(size_t)(r + 8) * D_ + k8 * 8 + 2 * tig];
            qf[t][k8][0] = __float_as_uint(a.x); qf[t][k8][2] = __float_as_uint(a.y);
            qf[t][k8][1] = __float_as_uint(b.x); qf[t][k8][3] = __float_as_uint(b.y);
        }
    }

    float m[2][2], l[2][2];
#pragma unroll
    for (int t = 0; t < 2; t++)
#pragma unroll
        for (int h = 0; h < 2; h++) { m[t][h] = -1e30f; l[t][h] = 0.f; }
    float o[2][8][4];
#pragma unroll
    for (int t = 0; t < 2; t++)
#pragma unroll
        for (int j = 0; j < 8; j++)
#pragma unroll
            for (int r = 0; r < 4; r++) o[t][j][r] = 0.f;

    const int frow = g * KST;

    for (int it = 0; it < S_ / 64; it++) {
        const int bf = it & 1;
        if (it + 1 < S_ / 64) PREFETCH((it + 1) * 64, bf ^ 1);
        CPCOMMIT();
        CPWAIT1();
        __syncthreads();

        const float* Ks = sm + bf * TILEF + frow + 2 * tig;
        const float* Vt = sm + (2 + bf) * TILEF + frow + 2 * tig;

        // ---- S = Q @ K^T : one LDS.64 per (k8,j) feeds BOTH q-tiles ----
        float s[2][8][4];
#pragma unroll
        for (int t = 0; t < 2; t++)
#pragma unroll
            for (int j = 0; j < 8; j++)
#pragma unroll
                for (int r = 0; r < 4; r++) s[t][j][r] = 0.f;
#pragma unroll
        for (int k8 = 0; k8 < 8; k8++) {
#pragma unroll
            for (int j = 0; j < 8; j++) {
                const float2 bv = *(const float2*)&Ks[j * 8 * KST + k8 * 8];
                const u32 b0 = __float_as_uint(bv.x), b1 = __float_as_uint(bv.y);
                mma8v(s[0][j], qf[0][k8][0], qf[0][k8][1], qf[0][k8][2], qf[0][k8][3], b0, b1);
                mma8v(s[1][j], qf[1][k8][0], qf[1][k8][1], qf[1][k8][2], qf[1][k8][3], b0, b1);
            }
        }

        // ---- online softmax in registers (per tile, rows g and g+8) ----
#pragma unroll
        for (int t = 0; t < 2; t++) {
#pragma unroll
            for (int h = 0; h < 2; h++) {
                float mx = -1e30f;
#pragma unroll
                for (int j = 0; j < 8; j++)
                    mx = fmaxf(mx, fmaxf(s[t][j][2 * h], s[t][j][2 * h + 1]));
                mx = fmaxf(mx, __shfl_xor_sync(0xffffffffu, mx, 1));
                mx = fmaxf(mx, __shfl_xor_sync(0xffffffffu, mx, 2));
                const float mn = fmaxf(m[t][h], mx);
                const float al = __expf(m[t][h] - mn);
                m[t][h] = mn;
                float rs = 0.f;
#pragma unroll
                for (int j = 0; j < 8; j++) {
                    s[t][j][2 * h]     = __expf(s[t][j][2 * h] - mn);
                    s[t][j][2 * h + 1] = __expf(s[t][j][2 * h + 1] - mn);
                    rs += s[t][j][2 * h] + s[t][j][2 * h + 1];
                }
                rs += __shfl_xor_sync(0xffffffffu, rs, 1);
                rs += __shfl_xor_sync(0xffffffffu, rs, 2);
                l[t][h] = l[t][h] * al + rs;
#pragma unroll
                for (int j = 0; j < 8; j++) {
                    o[t][j][2 * h] *= al;
                    o[t][j][2 * h + 1] *= al;
                }
            }
        }

        // ---- O += P @ V : one LDS.64 per (k8,j) feeds both tiles; P C-frag
        // feeds A-frag {c0,c2,c1,c3}, key perm absorbed by V pair loads ----
#pragma unroll
        for (int k8 = 0; k8 < 8; k8++) {
            u32 a[2][4];
#pragma unroll
            for (int t = 0; t < 2; t++) {
                a[t][0] = tf32b(s[t][k8][0]);
                a[t][1] = tf32b(s[t][k8][2]);
                a[t][2] = tf32b(s[t][k8][1]);
                a[t][3] = tf32b(s[t][k8][3]);
            }
#pragma unroll
            for (int j = 0; j < 8; j++) {
                const float2 bv = *(const float2*)&Vt[j * 8 * KST + k8 * 8];
                const u32 b0 = __float_as_uint(bv.x), b1 = __float_as_uint(bv.y);
                mma8v(o[0][j], a[0][0], a[0][1], a[0][2], a[0][3], b0, b1);
                mma8v(o[1][j], a[1][0], a[1][1], a[1][2], a[1][3], b0, b1);
            }
        }
        __syncthreads();   // done reading buffer bf before refill
    }

    // ---- normalize, write [B,S,E] ----
    const int b = bh >> 4, hd = bh & 15;
#pragma unroll
    for (int t = 0; t < 2; t++) {
#pragma unroll
        for (int h = 0; h < 2; h++) {
            const float inv = 1.0f / l[t][h];
            const int row = q0 + w * 32 + t * 16 + g + h * 8;
#pragma unroll
            for (int j = 0; j < 8; j++) {
                *(float2*)&AO[((size_t)(b * S_ + row)) * E_ + hd * D_ + j * 8 + 2 * tig] =
                    make_float2(o[t][j][2 * h] * inv, o[t][j][2 * h + 1] * inv);
            }
        }
    }
}

extern "C" void kernel_launch(void* const* d_in, const int* in_sizes, int n_in,
                              void* d_out, int out_size) {
    (void)in_sizes; (void)n_in; (void)out_size;
    const float* x  = (const float*)d_in[0];
    const float* wq = (const float*)d_in[1];
    const float* wk = (const float*)d_in[2];
    const float* wv = (const float*)d_in[3];
    const float* wo = (const float*)d_in[4];
    float* out = (float*)d_out;

    float *q, *k, *v, *ao;
    cudaGetSymbolAddress((void**)&q,  g_Q);
    cudaGetSymbolAddress((void**)&k,  g_K);
    cudaGetSymbolAddress((void**)&v,  g_V);
    cudaGetSymbolAddress((void**)&ao, g_AO);

    static int smem_set = 0;
    if (!smem_set) {
        cudaFuncSetAttribute(attn_mma, cudaFuncAttributeMaxDynamicSharedMemorySize,
                             SMEM_ATTN);
        smem_set = 1;
    }

    const dim3 gp(E_ / 128, (B_ * S_) / 128);   // (8, 32)
    gemm_mma<1><<<gp, 256>>>(x, wq, q, 0.125f);  // Q -> [B,H,S,D] perm, scaled
    gemm_mma<1><<<gp, 256>>>(x, wk, k, 1.0f);    // K -> [B,H,S,D] perm
    gemm_mma<2><<<gp, 256>>>(x, wv, v, 1.0f);    // V -> [B,H,D,S]
    attn_mma<<<dim3(S_ / 128, B_ * H_), 128, SMEM_ATTN>>>(q, k, v, ao);
    gemm_mma<0><<<gp, 256>>>(ao, wo, out, 1.0f); // out = AO @ wo^T
}

// round 16
// speedup vs baseline: 1.5338x; 1.5338x over previous
#include <cuda_runtime.h>
#include <math.h>

#define B_ 2
#define S_ 2048
#define E_ 1024
#define H_ 16
#define D_ 64

typedef unsigned int u32;

// Scratch (device globals — no allocation allowed in kernel_launch)
// g_Q/g_K: [B,H,S,D] with d-permutation pi (pairs (t,t+4) adjacent), tf32,
//          Q pre-scaled by 1/8.  g_V: [B,H,D,S] tf32.  Consumed only by attn.
__device__ float g_Q [B_ * S_ * E_];
__device__ float g_K [B_ * S_ * E_];
__device__ float g_V [B_ * S_ * E_];
__device__ float g_AO[B_ * S_ * E_];   // [B,S,E]

__device__ __forceinline__ u32 tf32b(float x) {   // tf32 (rna) bit pattern
    u32 r; asm("cvt.rna.tf32.f32 %0, %1;" : "=r"(r) : "f"(x));
    return r;
}
__device__ __forceinline__ float tf32r(float x) {
    return __uint_as_float(tf32b(x));
}
// D += A(16x8, row) * B(8x8, col)  -- tf32 inputs, fp32 accum (sm_80+ baseline)
__device__ __forceinline__ void mma8(float* c, const u32* a, const u32* b) {
    asm volatile(
        "mma.sync.aligned.m16n8k8.row.col.f32.tf32.tf32.f32 "
        "{%0,%1,%2,%3}, {%4,%5,%6,%7}, {%8,%9}, {%0,%1,%2,%3};"
        : "+f"(c[0]), "+f"(c[1]), "+f"(c[2]), "+f"(c[3])
        : "r"(a[0]), "r"(a[1]), "r"(a[2]), "r"(a[3]), "r"(b[0]), "r"(b[1]));
}
__device__ __forceinline__ void mma8v(float* c, u32 a0, u32 a1, u32 a2, u32 a3,
                                      u32 b0, u32 b1) {
    asm volatile(
        "mma.sync.aligned.m16n8k8.row.col.f32.tf32.tf32.f32 "
        "{%0,%1,%2,%3}, {%4,%5,%6,%7}, {%8,%9}, {%0,%1,%2,%3};"
        : "+f"(c[0]), "+f"(c[1]), "+f"(c[2]), "+f"(c[3])
        : "r"(a0), "r"(a1), "r"(a2), "r"(a3), "r"(b0), "r"(b1));
}
__device__ __forceinline__ u32 smem_u32(const void* p) {
    u32 a;
    asm("{ .reg .u64 t; cvta.to.shared.u64 t, %1; cvt.u32.u64 %0, t; }"
        : "=r"(a) : "l"(p));
    return a;
}
#define CP16(d, s) \
    asm volatile("cp.async.ca.shared.global [%0], [%1], 16;" :: "r"(d), "l"(s))
#define CPCOMMIT() asm volatile("cp.async.commit_group;" ::: "memory")
#define CPWAIT1()  asm volatile("cp.async.wait_group 1;" ::: "memory")

// d-permutation within each 8-group: t<4 -> 2t ; t>=4 -> 2(t-4)+1
__device__ __forceinline__ int dperm(int c) {
    const int t = c & 7;
    return (c & ~7) + ((t < 4) ? 2 * t : 2 * (t - 4) + 1);
}

// ============================================================================
// tf32 mma.sync GEMM: C[4096,1024] = A[M,K] @ Bw[N,K]^T
// CTA tile 128x128, BK=32, 8 warps (2m x 4n), warp tile 64x32.
// MODE 0: C[M,N] fp32.
// MODE 1: [B,H,S,D], tf32, scaled, d-PERMUTED (attention Q/K prep).
// MODE 2: [B,H,D,S], tf32 (V transposed for attention).
// ============================================================================
template <int MODE>
__global__ __launch_bounds__(256) void gemm_mma(const float* __restrict__ A,
                                                const float* __restrict__ Bw,
                                                float* __restrict__ C,
                                                float scale) {
    __shared__ float As[128][36];   // [m][k]
    __shared__ float Bs[128][36];   // [n][k]

    const int tid = threadIdx.x;
    const int wid = tid >> 5, lane = tid & 31;
    const int g = lane >> 2, tig = lane & 3;
    const int wm = wid >> 2, wn = wid & 3;
    const int m0 = blockIdx.y * 128, n0 = blockIdx.x * 128;

    const int row = tid >> 1, half = tid & 1;
    const float* pA = A  + (size_t)(m0 + row) * E_ + half * 16;
    const float* pB = Bw + (size_t)(n0 + row) * E_ + half * 16;

    float acc[4][4][4];
#pragma unroll
    for (int i = 0; i < 4; i++)
#pragma unroll
        for (int j = 0; j < 4; j++)
#pragma unroll
            for (int r = 0; r < 4; r++) acc[i][j][r] = 0.f;

    float4 fa[4], fb[4];
#pragma unroll
    for (int u = 0; u < 4; u++) {
        fa[u] = *(const float4*)(pA + u * 4);
        fb[u] = *(const float4*)(pB + u * 4);
    }

    for (int c = 0; c < 32; c++) {
#pragma unroll
        for (int u = 0; u < 4; u++) {
            const int kc = half * 16 + u * 4;
            *(float4*)&As[row][kc] = make_float4(tf32r(fa[u].x), tf32r(fa[u].y),
                                                 tf32r(fa[u].z), tf32r(fa[u].w));
            *(float4*)&Bs[row][kc] = make_float4(tf32r(fb[u].x), tf32r(fb[u].y),
                                                 tf32r(fb[u].z), tf32r(fb[u].w));
        }
        __syncthreads();
        if (c + 1 < 32) {
#pragma unroll
            for (int u = 0; u < 4; u++) {
                fa[u] = *(const float4*)(pA + (c + 1) * 32 + u * 4);
                fb[u] = *(const float4*)(pB + (c + 1) * 32 + u * 4);
            }
        }
#pragma unroll
        for (int k8 = 0; k8 < 32; k8 += 8) {
            u32 a[4][4], b[4][2];
#pragma unroll
            for (int mi = 0; mi < 4; mi++) {
                const int r = wm * 64 + mi * 16 + g;
                const u32* r0 = (const u32*)&As[r][k8 + tig];
                const u32* r1 = (const u32*)&As[r + 8][k8 + tig];
                a[mi][0] = r0[0]; a[mi][1] = r1[0];
                a[mi][2] = r0[4]; a[mi][3] = r1[4];
            }
#pragma unroll
            for (int ni = 0; ni < 4; ni++) {
                const int nn = wn * 32 + ni * 8 + g;
                const u32* r0 = (const u32*)&Bs[nn][k8 + tig];
                b[ni][0] = r0[0]; b[ni][1] = r0[4];
            }
#pragma unroll
            for (int mi = 0; mi < 4; mi++)
#pragma unroll
                for (int ni = 0; ni < 4; ni++)
                    mma8(acc[mi][ni], a[mi], b[ni]);
        }
        __syncthreads();
    }

#pragma unroll
    for (int mi = 0; mi < 4; mi++) {
#pragma unroll
        for (int hh = 0; hh < 2; hh++) {
            const int mg = m0 + wm * 64 + mi * 16 + g + hh * 8;
#pragma unroll
            for (int ni = 0; ni < 4; ni++) {
                const int col = n0 + wn * 32 + ni * 8 + 2 * tig;
                const float v0 = acc[mi][ni][hh * 2 + 0];
                const float v1 = acc[mi][ni][hh * 2 + 1];
                if (MODE == 0) {
                    *(float2*)&C[(size_t)mg * E_ + col] = make_float2(v0, v1);
                } else {
                    const int b = mg >> 11, s = mg & 2047;
                    const int h = col >> 6, d = col & 63;
                    if (MODE == 1) {   // d-permuted scalar stores
                        float* base = &C[((size_t)(b * H_ + h) * S_ + s) * D_];
                        base[dperm(d)]     = tf32r(v0 * scale);
                        base[dperm(d + 1)] = tf32r(v1 * scale);
                    } else {  // MODE 2: [B,H,D,S]
                        C[((size_t)(b * H_ + h) * D_ + d)     * S_ + s] = tf32r(v0 * scale);
                        C[((size_t)(b * H_ + h) * D_ + d + 1) * S_ + s] = tf32r(v1 * scale);
                    }
                }
            }
        }
    }
}

// ============================================================================
// tf32 mma.sync flash attention, cp.async double-buffered.
// CTA: 128 q-rows x one (b,h); 128 threads = 4 warps, EACH warp owns TWO
// 16-row q-tiles (32 q): every K/V B-fragment LDS.64 feeds 2 mmas.
// Each 64-key smem tile is processed as TWO 32-key subchunks
// (S-sub -> softmax update -> PV-sub) so the S buffer is [2][4][4]
// (32 regs, was 64) -> no spills at 2 CTAs/SM.
// Q/K arrive d-permuted (frag pairs adjacent); V as [D,S].
// Ks/Vt stride 72 (== 8 mod 32): 64-bit frag loads conflict-free per phase.
// ============================================================================
#define KST 72
#define TILEF (64 * KST)             // floats per array per stage
#define SMEM_ATTN (4 * TILEF * 4)    // K0,K1,V0,V1 = 73728 B

__global__ void __launch_bounds__(128, 2)
attn_mma(const float* __restrict__ Q, const float* __restrict__ K,
         const float* __restrict__ V, float* __restrict__ AO) {
    extern __shared__ __align__(16) float sm[];
    const int tid = threadIdx.x;
    const int w = tid >> 5, lane = tid & 31;
    const int g = lane >> 2, tig = lane & 3;
    const int bh = blockIdx.y;
    const int q0 = blockIdx.x * 128;

    const float* Qb = Q + (size_t)bh * S_ * D_;
    const float* Kb = K + (size_t)bh * S_ * D_;
    const float* Vb = V + (size_t)bh * D_ * S_;   // [D,S]

    const u32 sbase = smem_u32(sm);
    const int fr = tid >> 1;            // fill row (key / d)
    const int fh = (tid & 1) * 32;      // fill col half (floats)

#define PREFETCH(k0v, bbuf) do {                                               \
    const u32 kd = sbase + (u32)(((bbuf) * TILEF + fr * KST + fh) * 4);        \
    const float* ksrc = Kb + (size_t)((k0v) + fr) * D_ + fh;                   \
    const u32 vd = sbase + (u32)(((2 + (bbuf)) * TILEF + fr * KST + fh) * 4);  \
    const float* vsrc = Vb + (size_t)fr * S_ + (k0v) + fh;                     \
    _Pragma("unroll")                                                          \
    for (int c2 = 0; c2 < 8; c2++) {                                           \
        CP16(kd + c2 * 16, ksrc + c2 * 4);                                     \
        CP16(vd + c2 * 16, vsrc + c2 * 4);                                     \
    }                                                                          \
} while (0)

    PREFETCH(0, 0);
    CPCOMMIT();

    // ---- Q fragments for both tiles (permuted pairs -> 8B loads) ----
    u32 qf[2][8][4];
#pragma unroll
    for (int t = 0; t < 2; t++) {
        const int r = q0 + w * 32 + t * 16 + g;
#pragma unroll
        for (int k8 = 0; k8 < 8; k8++) {
            const float2 a = *(const float2*)&Qb[(size_t)r * D_ + k8 * 8 + 2 * tig];
            const float2 b = *(const float2*)&Qb[(size_t)(r + 8) * D_ + k8 * 8 + 2 * tig];
            qf[t][k8][0] = __float_as_uint(a.x); qf[t][k8][2] = __float_as_uint(a.y);
            qf[t][k8][1] = __float_as_uint(b.x); qf[t][k8][3] = __float_as_uint(b.y);
        }
    }

    float m[2][2], l[2][2];
#pragma unroll
    for (int t = 0; t < 2; t++)
#pragma unroll
        for (int h = 0; h < 2; h++) { m[t][h] = -1e30f; l[t][h] = 0.f; }
    float o[2][8][4];
#pragma unroll
    for (int t = 0; t < 2; t++)
#pragma unroll
        for (int j = 0; j < 8; j++)
#pragma unroll
            for (int r = 0; r < 4; r++) o[t][j][r] = 0.f;

    const int frow = g * KST;

    for (int it = 0; it < S_ / 64; it++) {
        const int bf = it & 1;
        if (it + 1 < S_ / 64) PREFETCH((it + 1) * 64, bf ^ 1);
        CPCOMMIT();
        CPWAIT1();
        __syncthreads();

        const float* Ks = sm + bf * TILEF + frow + 2 * tig;
        const float* Vt = sm + (2 + bf) * TILEF + frow + 2 * tig;

        // ---- two 32-key subchunks: S-sub -> softmax update -> PV-sub ----
#pragma unroll
        for (int sub = 0; sub < 2; sub++) {
            // S = Q @ K^T for keys [sub*32, sub*32+32)
            float s[2][4][4];
#pragma unroll
            for (int t = 0; t < 2; t++)
#pragma unroll
                for (int j = 0; j < 4; j++)
#pragma unroll
                    for (int r = 0; r < 4; r++) s[t][j][r] = 0.f;
#pragma unroll
            for (int k8 = 0; k8 < 8; k8++) {
#pragma unroll
                for (int j = 0; j < 4; j++) {
                    const float2 bv =
                        *(const float2*)&Ks[(sub * 4 + j) * 8 * KST + k8 * 8];
                    const u32 b0 = __float_as_uint(bv.x), b1 = __float_as_uint(bv.y);
                    mma8v(s[0][j], qf[0][k8][0], qf[0][k8][1], qf[0][k8][2],
                          qf[0][k8][3], b0, b1);
                    mma8v(s[1][j], qf[1][k8][0], qf[1][k8][1], qf[1][k8][2],
                          qf[1][k8][3], b0, b1);
                }
            }

            // online softmax update (per tile, rows g and g+8)
#pragma unroll
            for (int t = 0; t < 2; t++) {
#pragma unroll
                for (int h = 0; h < 2; h++) {
                    float mx = -1e30f;
#pragma unroll
                    for (int j = 0; j < 4; j++)
                        mx = fmaxf(mx, fmaxf(s[t][j][2 * h], s[t][j][2 * h + 1]));
                    mx = fmaxf(mx, __shfl_xor_sync(0xffffffffu, mx, 1));
                    mx = fmaxf(mx, __shfl_xor_sync(0xffffffffu, mx, 2));
                    const float mn = fmaxf(m[t][h], mx);
                    const float al = __expf(m[t][h] - mn);
                    m[t][h] = mn;
                    float rs = 0.f;
#pragma unroll
                    for (int j = 0; j < 4; j++) {
                        s[t][j][2 * h]     = __expf(s[t][j][2 * h] - mn);
                        s[t][j][2 * h + 1] = __expf(s[t][j][2 * h + 1] - mn);
                        rs += s[t][j][2 * h] + s[t][j][2 * h + 1];
                    }
                    rs += __shfl_xor_sync(0xffffffffu, rs, 1);
                    rs += __shfl_xor_sync(0xffffffffu, rs, 2);
                    l[t][h] = l[t][h] * al + rs;
#pragma unroll
                    for (int j = 0; j < 8; j++) {
                        o[t][j][2 * h] *= al;
                        o[t][j][2 * h + 1] *= al;
                    }
                }
            }

            // O += P @ V for this subchunk (kdim = 32 keys = 4 mma steps);
            // P C-frag feeds A-frag {c0,c2,c1,c3}, key perm absorbed by
            // V pair loads Vt[d][sub*32 + k8*8 + 2tig]
#pragma unroll
            for (int k8 = 0; k8 < 4; k8++) {
                u32 a[2][4];
#pragma unroll
                for (int t = 0; t < 2; t++) {
                    a[t][0] = tf32b(s[t][k8][0]);
                    a[t][1] = tf32b(s[t][k8][2]);
                    a[t][2] = tf32b(s[t][k8][1]);
                    a[t][3] = tf32b(s[t][k8][3]);
                }
#pragma unroll
                for (int j = 0; j < 8; j++) {
                    const float2 bv =
                        *(const float2*)&Vt[j * 8 * KST + sub * 32 + k8 * 8];
                    const u32 b0 = __float_as_uint(bv.x), b1 = __float_as_uint(bv.y);
                    mma8v(o[0][j], a[0][0], a[0][1], a[0][2], a[0][3], b0, b1);
                    mma8v(o[1][j], a[1][0], a[1][1], a[1][2], a[1][3], b0, b1);
                }
            }
        }
        __syncthreads();   // done reading buffer bf before refill
    }

    // ---- normalize, write [B,S,E] ----
    const int b = bh >> 4, hd = bh & 15;
#pragma unroll
    for (int t = 0; t < 2; t++) {
#pragma unroll
        for (int h = 0; h < 2; h++) {
            const float inv = 1.0f / l[t][h];
            const int row = q0 + w * 32 + t * 16 + g + h * 8;
#pragma unroll
            for (int j = 0; j < 8; j++) {
                *(float2*)&AO[((size_t)(b * S_ + row)) * E_ + hd * D_ + j * 8 + 2 * tig] =
                    make_float2(o[t][j][2 * h] * inv, o[t][j][2 * h + 1] * inv);
            }
        }
    }
}

extern "C" void kernel_launch(void* const* d_in, const int* in_sizes, int n_in,
                              void* d_out, int out_size) {
    (void)in_sizes; (void)n_in; (void)out_size;
    const float* x  = (const float*)d_in[0];
    const float* wq = (const float*)d_in[1];
    const float* wk = (const float*)d_in[2];
    const float* wv = (const float*)d_in[3];
    const float* wo = (const float*)d_in[4];
    float* out = (float*)d_out;

    float *q, *k, *v, *ao;
    cudaGetSymbolAddress((void**)&q,  g_Q);
    cudaGetSymbolAddress((void**)&k,  g_K);
    cudaGetSymbolAddress((void**)&v,  g_V);
    cudaGetSymbolAddress((void**)&ao, g_AO);

    static int smem_set = 0;
    if (!smem_set) {
        cudaFuncSetAttribute(attn_mma, cudaFuncAttributeMaxDynamicSharedMemorySize,
                             SMEM_ATTN);
        smem_set = 1;
    }

    const dim3 gp(E_ / 128, (B_ * S_) / 128);   // (8, 32)
    gemm_mma<1><<<gp, 256>>>(x, wq, q, 0.125f);  // Q -> [B,H,S,D] perm, scaled
    gemm_mma<1><<<gp, 256>>>(x, wk, k, 1.0f);    // K -> [B,H,S,D] perm
    gemm_mma<2><<<gp, 256>>>(x, wv, v, 1.0f);    // V -> [B,H,D,S]
    attn_mma<<<dim3(S_ / 128, B_ * H_), 128, SMEM_ATTN>>>(q, k, v, ao);
    gemm_mma<0><<<gp, 256>>>(ao, wo, out, 1.0f); // out = AO @ wo^T
}

// round 17
// speedup vs baseline: 1.7256x; 1.1250x over previous
#include <cuda_runtime.h>
#include <math.h>

#define B_ 2
#define S_ 2048
#define E_ 1024
#define H_ 16
#define D_ 64

typedef unsigned int u32;

// Scratch (device globals — no allocation allowed in kernel_launch)
__device__ float g_X [B_ * S_ * E_];   // tf32-rounded x
__device__ float g_Wq[E_ * E_];        // tf32-rounded weights
__device__ float g_Wk[E_ * E_];
__device__ float g_Wv[E_ * E_];
__device__ float g_Wo[E_ * E_];
// g_Q/g_K: [B,H,S,D] d-permuted, tf32; Q pre-scaled 1/8.  g_V: [B,H,D,S] tf32.
__device__ float g_Q [B_ * S_ * E_];
__device__ float g_K [B_ * S_ * E_];
__device__ float g_V [B_ * S_ * E_];
__device__ float g_AO[B_ * S_ * E_];   // [B,S,E], tf32-rounded by attn epilogue

__device__ __forceinline__ u32 tf32b(float x) {   // tf32 (rna) bit pattern
    u32 r; asm("cvt.rna.tf32.f32 %0, %1;" : "=r"(r) : "f"(x));
    return r;
}
__device__ __forceinline__ float tf32r(float x) {
    return __uint_as_float(tf32b(x));
}
__device__ __forceinline__ void mma8v(float* c, u32 a0, u32 a1, u32 a2, u32 a3,
                                      u32 b0, u32 b1) {
    asm volatile(
        "mma.sync.aligned.m16n8k8.row.col.f32.tf32.tf32.f32 "
        "{%0,%1,%2,%3}, {%4,%5,%6,%7}, {%8,%9}, {%0,%1,%2,%3};"
        : "+f"(c[0]), "+f"(c[1]), "+f"(c[2]), "+f"(c[3])
        : "r"(a0), "r"(a1), "r"(a2), "r"(a3), "r"(b0), "r"(b1));
}
__device__ __forceinline__ u32 smem_u32(const void* p) {
    u32 a;
    asm("{ .reg .u64 t; cvta.to.shared.u64 t, %1; cvt.u32.u64 %0, t; }"
        : "=r"(a) : "l"(p));
    return a;
}
#define CP16(d, s) \
    asm volatile("cp.async.ca.shared.global [%0], [%1], 16;" :: "r"(d), "l"(s))
#define CPCOMMIT() asm volatile("cp.async.commit_group;" ::: "memory")
#define CPWAIT1()  asm volatile("cp.async.wait_group 1;" ::: "memory")

// d-permutation within each 8-group: t<4 -> 2t ; t>=4 -> 2(t-4)+1
__device__ __forceinline__ int dperm(int c) {
    const int t = c & 7;
    return (c & ~7) + ((t < 4) ? 2 * t : 2 * (t - 4) + 1);
}

// ============================================================================
// prep: tf32-round x and the four weight matrices into scratch.
// ============================================================================
__global__ void prep_round(const float* __restrict__ x,  const float* __restrict__ wq,
                           const float* __restrict__ wk, const float* __restrict__ wv,
                           const float* __restrict__ wo) {
    const int NX = B_ * S_ * E_;      // 4M
    const int NW = E_ * E_;           // 1M
    for (int i = blockIdx.x * blockDim.x + threadIdx.x; i < NX + 4 * NW;
         i += gridDim.x * blockDim.x) {
        if (i < NX) { g_X[i] = tf32r(x[i]); continue; }
        const int j = i - NX;
        const int seg = j >> 20, k = j & (NW - 1);
        if      (seg == 0) g_Wq[k] = tf32r(wq[k]);
        else if (seg == 1) g_Wk[k] = tf32r(wk[k]);
        else if (seg == 2) g_Wv[k] = tf32r(wv[k]);
        else               g_Wo[k] = tf32r(wo[k]);
    }
}

// ============================================================================
// tf32 mma.sync GEMM v2: C[4096,1024] = A[M,K] @ Bw[N,K]^T
// Inputs PRE-tf32-ROUNDED.  CTA tile 128x128, BK=32, 128 threads = 4 warps
// (2m x 2n), warp tile 64x64 (mi 4 x ni 8): 1.0 LDS per mma.
// cp.async double-buffered fills (no register staging).
// Grid 256 CTAs @ 2/SM = one wave.
// smem [row][36]: frag banks 4g+8k8'+tig all distinct; fills conflict-free.
// MODE 0: C[M,N] fp32. MODE 1: [B,H,S,D] tf32, scaled, d-permuted.
// MODE 2: [B,H,D,S] tf32.
// ============================================================================
#define GTILE (128 * 36)
#define GSMEM (4 * GTILE * 4)   // A0,A1,B0,B1 = 73728 B

template <int MODE>
__global__ void __launch_bounds__(128, 2)
gemm_mma(const float* __restrict__ A, const float* __restrict__ Bw,
         float* __restrict__ C, float scale) {
    extern __shared__ __align__(16) float gsm[];
    const int tid = threadIdx.x;
    const int wid = tid >> 5, lane = tid & 31;
    const int g = lane >> 2, tig = lane & 3;
    const int wm = wid >> 1, wn = wid & 1;
    const int m0 = blockIdx.y * 128, n0 = blockIdx.x * 128;

    const u32 sb = smem_u32(gsm);
    const int frow = tid >> 2;          // 0..31
    const int fcol = (tid & 3) * 8;     // 0,8,16,24

#define GPREF(cc, buf) do {                                                    \
    _Pragma("unroll")                                                          \
    for (int p = 0; p < 4; p++) {                                              \
        const int row = p * 32 + frow;                                         \
        const u32 da = sb + (u32)(((buf) * GTILE + row * 36 + fcol) * 4);      \
        const float* sa = A + (size_t)(m0 + row) * E_ + (cc) * 32 + fcol;      \
        const u32 db = sb + (u32)(((2 + (buf)) * GTILE + row * 36 + fcol) * 4);\
        const float* sbp = Bw + (size_t)(n0 + row) * E_ + (cc) * 32 + fcol;    \
        CP16(da, sa); CP16(da + 16, sa + 4);                                   \
        CP16(db, sbp); CP16(db + 16, sbp + 4);                                 \
    }                                                                          \
} while (0)

    GPREF(0, 0);
    CPCOMMIT();

    float acc[4][8][4];
#pragma unroll
    for (int i = 0; i < 4; i++)
#pragma unroll
        for (int j = 0; j < 8; j++)
#pragma unroll
            for (int r = 0; r < 4; r++) acc[i][j][r] = 0.f;

    for (int c = 0; c < 32; c++) {
        const int buf = c & 1;
        if (c + 1 < 32) GPREF(c + 1, buf ^ 1);
        CPCOMMIT();
        CPWAIT1();
        __syncthreads();

        const float* As = gsm + buf * GTILE;
        const float* Bs = gsm + (2 + buf) * GTILE;

#pragma unroll
        for (int k8 = 0; k8 < 4; k8++) {
            u32 a[4][4], b[8][2];
#pragma unroll
            for (int mi = 0; mi < 4; mi++) {
                const int r = wm * 64 + mi * 16 + g;
                const float* p0 = &As[r * 36 + k8 * 8 + tig];
                const float* p1 = &As[(r + 8) * 36 + k8 * 8 + tig];
                a[mi][0] = __float_as_uint(p0[0]);
                a[mi][1] = __float_as_uint(p1[0]);
                a[mi][2] = __float_as_uint(p0[4]);
                a[mi][3] = __float_as_uint(p1[4]);
            }
#pragma unroll
            for (int ni = 0; ni < 8; ni++) {
                const int nn = wn * 64 + ni * 8 + g;
                const float* p0 = &Bs[nn * 36 + k8 * 8 + tig];
                b[ni][0] = __float_as_uint(p0[0]);
                b[ni][1] = __float_as_uint(p0[4]);
            }
#pragma unroll
            for (int mi = 0; mi < 4; mi++)
#pragma unroll
                for (int ni = 0; ni < 8; ni++)
                    mma8v(acc[mi][ni], a[mi][0], a[mi][1], a[mi][2], a[mi][3],
                          b[ni][0], b[ni][1]);
        }
        __syncthreads();
    }

    // ------------------------------ epilogue ------------------------------
#pragma unroll
    for (int mi = 0; mi < 4; mi++) {
#pragma unroll
        for (int hh = 0; hh < 2; hh++) {
            const int mg = m0 + wm * 64 + mi * 16 + g + hh * 8;
#pragma unroll
            for (int ni = 0; ni < 8; ni++) {
                const int col = n0 + wn * 64 + ni * 8 + 2 * tig;
                const float v0 = acc[mi][ni][hh * 2 + 0];
                const float v1 = acc[mi][ni][hh * 2 + 1];
                if (MODE == 0) {
                    *(float2*)&C[(size_t)mg * E_ + col] = make_float2(v0, v1);
                } else {
                    const int b = mg >> 11, s = mg & 2047;
                    const int h = col >> 6, d = col & 63;
                    if (MODE == 1) {   // d-permuted scalar stores
                        float* base = &C[((size_t)(b * H_ + h) * S_ + s) * D_];
                        base[dperm(d)]     = tf32r(v0 * scale);
                        base[dperm(d + 1)] = tf32r(v1 * scale);
                    } else {  // MODE 2: [B,H,D,S]
                        C[((size_t)(b * H_ + h) * D_ + d)     * S_ + s] = tf32r(v0 * scale);
                        C[((size_t)(b * H_ + h) * D_ + d + 1) * S_ + s] = tf32r(v1 * scale);
                    }
                }
            }
        }
    }
}

// ============================================================================
// tf32 mma.sync flash attention (round-16 version, unchanged except AO is
// tf32-rounded at the epilogue so the final GEMM can consume it raw).
// ============================================================================
#define KST 72
#define TILEF (64 * KST)
#define SMEM_ATTN (4 * TILEF * 4)    // 73728 B

__global__ void __launch_bounds__(128, 2)
attn_mma(const float* __restrict__ Q, const float* __restrict__ K,
         const float* __restrict__ V, float* __restrict__ AO) {
    extern __shared__ __align__(16) float sm[];
    const int tid = threadIdx.x;
    const int w = tid >> 5, lane = tid & 31;
    const int g = lane >> 2, tig = lane & 3;
    const int bh = blockIdx.y;
    const int q0 = blockIdx.x * 128;

    const float* Qb = Q + (size_t)bh * S_ * D_;
    const float* Kb = K + (size_t)bh * S_ * D_;
    const float* Vb = V + (size_t)bh * D_ * S_;   // [D,S]

    const u32 sbase = smem_u32(sm);
    const int fr = tid >> 1;
    const int fh = (tid & 1) * 32;

#define PREFETCH(k0v, bbuf) do {                                               \
    const u32 kd = sbase + (u32)(((bbuf) * TILEF + fr * KST + fh) * 4);        \
    const float* ksrc = Kb + (size_t)((k0v) + fr) * D_ + fh;                   \
    const u32 vd = sbase + (u32)(((2 + (bbuf)) * TILEF + fr * KST + fh) * 4);  \
    const float* vsrc = Vb + (size_t)fr * S_ + (k0v) + fh;                     \
    _Pragma("unroll")                                                          \
    for (int c2 = 0; c2 < 8; c2++) {                                           \
        CP16(kd + c2 * 16, ksrc + c2 * 4);                                     \
        CP16(vd + c2 * 16, vsrc + c2 * 4);                                     \
    }                                                                          \
} while (0)

    PREFETCH(0, 0);
    CPCOMMIT();

    u32 qf[2][8][4];
#pragma unroll
    for (int t = 0; t < 2; t++) {
        const int r = q0 + w * 32 + t * 16 + g;
#pragma unroll
        for (int k8 = 0; k8 < 8; k8++) {
            const float2 a = *(const float2*)&Qb[(size_t)r * D_ + k8 * 8 + 2 * tig];
            const float2 b = *(const float2*)&Qb[(size_t)(r + 8) * D_ + k8 * 8 + 2 * tig];
            qf[t][k8][0] = __float_as_uint(a.x); qf[t][k8][2] = __float_as_uint(a.y);
            qf[t][k8][1] = __float_as_uint(b.x); qf[t][k8][3] = __float_as_uint(b.y);
        }
    }

    float m[2][2], l[2][2];
#pragma unroll
    for (int t = 0; t < 2; t++)
#pragma unroll
        for (int h = 0; h < 2; h++) { m[t][h] = -1e30f; l[t][h] = 0.f; }
    float o[2][8][4];
#pragma unroll
    for (int t = 0; t < 2; t++)
#pragma unroll
        for (int j = 0; j < 8; j++)
#pragma unroll
            for (int r = 0; r < 4; r++) o[t][j][r] = 0.f;

    const int frow = g * KST;

    for (int it = 0; it < S_ / 64; it++) {
        const int bf = it & 1;
        if (it + 1 < S_ / 64) PREFETCH((it + 1) * 64, bf ^ 1);
        CPCOMMIT();
        CPWAIT1();
        __syncthreads();

        const float* Ks = sm + bf * TILEF + frow + 2 * tig;
        const float* Vt = sm + (2 + bf) * TILEF + frow + 2 * tig;

#pragma unroll
        for (int sub = 0; sub < 2; sub++) {
            float s[2][4][4];
#pragma unroll
            for (int t = 0; t < 2; t++)
#pragma unroll
                for (int j = 0; j < 4; j++)
#pragma unroll
                    for (int r = 0; r < 4; r++) s[t][j][r] = 0.f;
#pragma unroll
            for (int k8 = 0; k8 < 8; k8++) {
#pragma unroll
                for (int j = 0; j < 4; j++) {
                    const float2 bv =
                        *(const float2*)&Ks[(sub * 4 + j) * 8 * KST + k8 * 8];
                    const u32 b0 = __float_as_uint(bv.x), b1 = __float_as_uint(bv.y);
                    mma8v(s[0][j], qf[0][k8][0], qf[0][k8][1], qf[0][k8][2],
                          qf[0][k8][3], b0, b1);
                    mma8v(s[1][j], qf[1][k8][0], qf[1][k8][1], qf[1][k8][2],
                          qf[1][k8][3], b0, b1);
                }
            }

#pragma unroll
            for (int t = 0; t < 2; t++) {
#pragma unroll
                for (int h = 0; h < 2; h++) {
                    float mx = -1e30f;
#pragma unroll
                    for (int j = 0; j < 4; j++)
                        mx = fmaxf(mx, fmaxf(s[t][j][2 * h], s[t][j][2 * h + 1]));
                    mx = fmaxf(mx, __shfl_xor_sync(0xffffffffu, mx, 1));
                    mx = fmaxf(mx, __shfl_xor_sync(0xffffffffu, mx, 2));
                    const float mn = fmaxf(m[t][h], mx);
                    const float al = __expf(m[t][h] - mn);
                    m[t][h] = mn;
                    float rs = 0.f;
#pragma unroll
                    for (int j = 0; j < 4; j++) {
                        s[t][j][2 * h]     = __expf(s[t][j][2 * h] - mn);
                        s[t][j][2 * h + 1] = __expf(s[t][j][2 * h + 1] - mn);
                        rs += s[t][j][2 * h] + s[t][j][2 * h + 1];
                    }
                    rs += __shfl_xor_sync(0xffffffffu, rs, 1);
                    rs += __shfl_xor_sync(0xffffffffu, rs, 2);
                    l[t][h] = l[t][h] * al + rs;
#pragma unroll
                    for (int j = 0; j < 8; j++) {
                        o[t][j][2 * h] *= al;
                        o[t][j][2 * h + 1] *= al;
                    }
                }
            }

#pragma unroll
            for (int k8 = 0; k8 < 4; k8++) {
                u32 a[2][4];
#pragma unroll
                for (int t = 0; t < 2; t++) {
                    a[t][0] = tf32b(s[t][k8][0]);
                    a[t][1] = tf32b(s[t][k8][2]);
                    a[t][2] = tf32b(s[t][k8][1]);
                    a[t][3] = tf32b(s[t][k8][3]);
                }
#pragma unroll
                for (int j = 0; j < 8; j++) {
                    const float2 bv =
                        *(const float2*)&Vt[j * 8 * KST + sub * 32 + k8 * 8];
                    const u32 b0 = __float_as_uint(bv.x), b1 = __float_as_uint(bv.y);
                    mma8v(o[0][j], a[0][0], a[0][1], a[0][2], a[0][3], b0, b1);
                    mma8v(o[1][j], a[1][0], a[1][1], a[1][2], a[1][3], b0, b1);
                }
            }
        }
        __syncthreads();
    }

    // ---- normalize, tf32-round (final GEMM consumes raw), write [B,S,E] ----
    const int b = bh >> 4, hd = bh & 15;
#pragma unroll
    for (int t = 0; t < 2; t++) {
#pragma unroll
        for (int h = 0; h < 2; h++) {
            const float inv = 1.0f / l[t][h];
            const int row = q0 + w * 32 + t * 16 + g + h * 8;
#pragma unroll
            for (int j = 0; j < 8; j++) {
                *(float2*)&AO[((size_t)(b * S_ + row)) * E_ + hd * D_ + j * 8 + 2 * tig] =
                    make_float2(tf32r(o[t][j][2 * h] * inv),
                                tf32r(o[t][j][2 * h + 1] * inv));
            }
        }
    }
}

extern "C" void kernel_launch(void* const* d_in, const int* in_sizes, int n_in,
                              void* d_out, int out_size) {
    (void)in_sizes; (void)n_in; (void)out_size;
    const float* x  = (const float*)d_in[0];
    const float* wq = (const float*)d_in[1];
    const float* wk = (const float*)d_in[2];
    const float* wv = (const float*)d_in[3];
    const float* wo = (const float*)d_in[4];
    float* out = (float*)d_out;

    float *xr, *wqr, *wkr, *wvr, *wor, *q, *k, *v, *ao;
    cudaGetSymbolAddress((void**)&xr,  g_X);
    cudaGetSymbolAddress((void**)&wqr, g_Wq);
    cudaGetSymbolAddress((void**)&wkr, g_Wk);
    cudaGetSymbolAddress((void**)&wvr, g_Wv);
    cudaGetSymbolAddress((void**)&wor, g_Wo);
    cudaGetSymbolAddress((void**)&q,   g_Q);
    cudaGetSymbolAddress((void**)&k,   g_K);
    cudaGetSymbolAddress((void**)&v,   g_V);
    cudaGetSymbolAddress((void**)&ao,  g_AO);

    static int smem_set = 0;
    if (!smem_set) {
        cudaFuncSetAttribute(attn_mma, cudaFuncAttributeMaxDynamicSharedMemorySize,
                             SMEM_ATTN);
        cudaFuncSetAttribute(gemm_mma<0>, cudaFuncAttributeMaxDynamicSharedMemorySize,
                             GSMEM);
        cudaFuncSetAttribute(gemm_mma<1>, cudaFuncAttributeMaxDynamicSharedMemorySize,
                             GSMEM);
        cudaFuncSetAttribute(gemm_mma<2>, cudaFuncAttributeMaxDynamicSharedMemorySize,
                             GSMEM);
        smem_set = 1;
    }

    prep_round<<<512, 1024>>>(x, wq, wk, wv, wo);

    const dim3 gp(E_ / 128, (B_ * S_) / 128);   // (8, 32) = 256 CTAs, one wave
    gemm_mma<1><<<gp, 128, GSMEM>>>(xr, wqr, q, 0.125f);  // Q perm, scaled
    gemm_mma<1><<<gp, 128, GSMEM>>>(xr, wkr, k, 1.0f);    // K perm
    gemm_mma<2><<<gp, 128, GSMEM>>>(xr, wvr, v, 1.0f);    // V -> [B,H,D,S]
    attn_mma<<<dim3(S_ / 128, B_ * H_), 128, SMEM_ATTN>>>(q, k, v, ao);
    gemm_mma<0><<<gp, 128, GSMEM>>>(ao, wor, out, 1.0f);  // out = AO @ wo^T
}